// round 6
// baseline (speedup 1.0000x reference)
#include <cuda_runtime.h>
#include <cuda_bf16.h>

// Problem constants
#define PB 2
#define PL 2048
#define PD 1024
#define PH 16
#define PDh 64
#define PM (PB * PL)   // 4096 rows

// Scratch (device globals; no runtime allocation allowed)
__device__ float g_q[PM * PD];
__device__ float g_k[PM * PD];
__device__ float g_v[PM * PD];
__device__ float g_o[PM * PD];

// ---------------------------------------------------------------------------
// SIMT tiled GEMM: C[M,N] = A[M,K] * B[K,N], row-major, fp32.
// 128x128 block tile, K-tile 16, 8x8 thread tile, 256 threads.
// ---------------------------------------------------------------------------
#define GBM 128
#define GBN 128
#define GBK 16

__device__ __forceinline__ void gemm_body(const float* __restrict__ A,
                                          const float* __restrict__ B,
                                          float* __restrict__ C,
                                          int M, int N, int K) {
    __shared__ float As[GBK][GBM];   // transposed A tile
    __shared__ float Bs[GBK][GBN];

    const int tid = threadIdx.x;
    const int tx = tid & 15;          // 0..15 -> column groups
    const int ty = tid >> 4;          // 0..15 -> row groups
    const int rowBase = blockIdx.y * GBM;
    const int colBase = blockIdx.x * GBN;

    float acc[8][8];
#pragma unroll
    for (int i = 0; i < 8; i++)
#pragma unroll
        for (int j = 0; j < 8; j++) acc[i][j] = 0.f;

    for (int kt = 0; kt < K; kt += GBK) {
        // Load A tile (128 rows x 16 cols): 512 float4 / 256 threads = 2 each
#pragma unroll
        for (int i = 0; i < 2; i++) {
            int lin = tid + i * 256;       // 0..511
            int r = lin >> 2;              // 0..127
            int c4 = (lin & 3) * 4;        // 0,4,8,12
            float4 a = *(const float4*)&A[(size_t)(rowBase + r) * K + kt + c4];
            As[c4 + 0][r] = a.x;
            As[c4 + 1][r] = a.y;
            As[c4 + 2][r] = a.z;
            As[c4 + 3][r] = a.w;
        }
        // Load B tile (16 rows x 128 cols): 512 float4 / 256 threads = 2 each
#pragma unroll
        for (int i = 0; i < 2; i++) {
            int lin = tid + i * 256;       // 0..511
            int r = lin >> 5;              // 0..15
            int c4 = (lin & 31) * 4;       // 0..124
            *(float4*)&Bs[r][c4] = *(const float4*)&B[(size_t)(kt + r) * N + colBase + c4];
        }
        __syncthreads();

#pragma unroll
        for (int k = 0; k < GBK; k++) {
            float ra[8], rb[8];
            *(float4*)&ra[0] = *(const float4*)&As[k][ty * 8];
            *(float4*)&ra[4] = *(const float4*)&As[k][ty * 8 + 4];
            *(float4*)&rb[0] = *(const float4*)&Bs[k][tx * 8];
            *(float4*)&rb[4] = *(const float4*)&Bs[k][tx * 8 + 4];
#pragma unroll
            for (int i = 0; i < 8; i++)
#pragma unroll
                for (int j = 0; j < 8; j++) acc[i][j] += ra[i] * rb[j];
        }
        __syncthreads();
    }

    // Write back
#pragma unroll
    for (int i = 0; i < 8; i++) {
        int r = rowBase + ty * 8 + i;
        float* crow = &C[(size_t)r * N + colBase + tx * 8];
        *(float4*)&crow[0] = *(const float4*)&acc[i][0];
        *(float4*)&crow[4] = *(const float4*)&acc[i][4];
    }
}

// QKV projection: grid.z selects weight/output
__global__ __launch_bounds__(256) void qkv_gemm_kernel(const float* __restrict__ x,
                                                       const float* __restrict__ Wq,
                                                       const float* __restrict__ Wk,
                                                       const float* __restrict__ Wv) {
    const float* Bw = (blockIdx.z == 0) ? Wq : (blockIdx.z == 1) ? Wk : Wv;
    float* C = (blockIdx.z == 0) ? g_q : (blockIdx.z == 1) ? g_k : g_v;
    gemm_body(x, Bw, C, PM, PD, PD);
}

__global__ __launch_bounds__(256) void out_gemm_kernel(const float* __restrict__ Wout,
                                                       float* __restrict__ out) {
    gemm_body(g_o, Wout, out, PM, PD, PD);
}

// ---------------------------------------------------------------------------
// Flash attention (causal), fp32.
// Block: 128 threads, each thread owns ONE query row (q + O acc in registers).
// K/V tiles of 64 keys in SMEM; online softmax over 16-key chunks.
// grid: (L/128, H, B)
// ---------------------------------------------------------------------------
#define AT_BM 128
#define AT_BN 64

__global__ __launch_bounds__(128) void attn_kernel() {
    const int qb = blockIdx.x * AT_BM;
    const int h  = blockIdx.y;
    const int b  = blockIdx.z;
    const int t  = threadIdx.x;
    const int i  = qb + t;                    // this thread's query row

    __shared__ float4 k_sm[AT_BN][PDh / 4];   // [key][16]
    __shared__ float4 v_sm[AT_BN][PDh / 4];

    // Load q row into registers, pre-scaled by 1/sqrt(Dh)
    const float sc = 0.125f;
    const float4* qptr = (const float4*)(g_q + ((size_t)(b * PL + i)) * PD + h * PDh);
    float4 q[16];
#pragma unroll
    for (int e = 0; e < 16; e++) {
        float4 v = qptr[e];
        v.x *= sc; v.y *= sc; v.z *= sc; v.w *= sc;
        q[e] = v;
    }

    float4 acc[16];
#pragma unroll
    for (int e = 0; e < 16; e++) acc[e] = make_float4(0.f, 0.f, 0.f, 0.f);
    float m = -1e30f, l = 0.f;

    const int imax = qb + AT_BM - 1;

    for (int jb = 0; jb <= imax; jb += AT_BN) {
        // Cooperative K/V tile load: 64 rows x 16 float4 each.
        {
            int r = t >> 1;
            int half8 = (t & 1) * 8;
            const float4* kg = (const float4*)(g_k + ((size_t)(b * PL + jb + r)) * PD + h * PDh);
            const float4* vg = (const float4*)(g_v + ((size_t)(b * PL + jb + r)) * PD + h * PDh);
#pragma unroll
            for (int w = 0; w < 8; w++) {
                k_sm[r][half8 + w] = kg[half8 + w];
                v_sm[r][half8 + w] = vg[half8 + w];
            }
        }
        __syncthreads();

#pragma unroll
        for (int c = 0; c < 4; c++) {
            const int jstart = jb + c * 16;
            if (jstart <= i) {
                float s[16];
#pragma unroll
                for (int jj = 0; jj < 16; jj++) {
                    const int j = c * 16 + jj;
                    float s0 = 0.f, s1 = 0.f, s2 = 0.f, s3 = 0.f;
#pragma unroll
                    for (int e = 0; e < 16; e++) {
                        float4 kv = k_sm[j][e];
                        s0 += q[e].x * kv.x;
                        s1 += q[e].y * kv.y;
                        s2 += q[e].z * kv.z;
                        s3 += q[e].w * kv.w;
                    }
                    float sum = (s0 + s1) + (s2 + s3);
                    s[jj] = (jstart + jj <= i) ? sum : -1e30f;
                }
                // chunk max
                float cm = s[0];
#pragma unroll
                for (int jj = 1; jj < 16; jj++) cm = fmaxf(cm, s[jj]);
                float nm = fmaxf(m, cm);
                float corr = __expf(m - nm);
                l *= corr;
#pragma unroll
                for (int e = 0; e < 16; e++) {
                    acc[e].x *= corr; acc[e].y *= corr;
                    acc[e].z *= corr; acc[e].w *= corr;
                }
#pragma unroll
                for (int jj = 0; jj < 16; jj++) {
                    const int j = c * 16 + jj;
                    float p = __expf(s[jj] - nm);
                    l += p;
#pragma unroll
                    for (int e = 0; e < 16; e++) {
                        float4 vv = v_sm[j][e];
                        acc[e].x += p * vv.x;
                        acc[e].y += p * vv.y;
                        acc[e].z += p * vv.z;
                        acc[e].w += p * vv.w;
                    }
                }
                m = nm;
            }
        }
        __syncthreads();
    }

    const float inv = 1.f / l;
    float4* optr = (float4*)(g_o + ((size_t)(b * PL + i)) * PD + h * PDh);
#pragma unroll
    for (int e = 0; e < 16; e++) {
        float4 r;
        r.x = acc[e].x * inv; r.y = acc[e].y * inv;
        r.z = acc[e].z * inv; r.w = acc[e].w * inv;
        optr[e] = r;
    }
}

// ---------------------------------------------------------------------------
// Launch
// ---------------------------------------------------------------------------
extern "C" void kernel_launch(void* const* d_in, const int* in_sizes, int n_in,
                              void* d_out, int out_size) {
    const float* x    = (const float*)d_in[0];
    const float* Wq   = (const float*)d_in[1];
    const float* Wk   = (const float*)d_in[2];
    const float* Wv   = (const float*)d_in[3];
    const float* Wout = (const float*)d_in[4];
    float* out = (float*)d_out;

    // QKV projections: 3 GEMMs of (4096x1024)x(1024x1024)
    dim3 gemmGrid(PD / GBN, PM / GBM, 3);
    qkv_gemm_kernel<<<gemmGrid, 256>>>(x, Wq, Wk, Wv);

    // Causal flash attention
    dim3 attnGrid(PL / AT_BM, PH, PB);
    attn_kernel<<<attnGrid, 128>>>();

    // Output projection
    dim3 outGrid(PD / GBN, PM / GBM, 1);
    out_gemm_kernel<<<outGrid, 256>>>(Wout, out);
}

// round 10
// speedup vs baseline: 1.0054x; 1.0054x over previous
#include <cuda_runtime.h>
#include <cuda_bf16.h>

// Problem constants
#define PB 2
#define PL 2048
#define PD 1024
#define PH 16
#define PDh 64
#define PM (PB * PL)   // 4096 rows

// Scratch (device globals; no runtime allocation allowed)
__device__ float g_q[PM * PD];
__device__ float g_k[PM * PD];
__device__ float g_v[PM * PD];
__device__ float g_o[PM * PD];

// ---------------------------------------------------------------------------
// SIMT tiled GEMM: C[M,N] = A[M,K] * B[K,N], row-major, fp32.
// 128x128 block tile, K-tile 16, 8x8 thread tile, 256 threads.
// ---------------------------------------------------------------------------
#define GBM 128
#define GBN 128
#define GBK 16

__device__ __forceinline__ void gemm_body(const float* __restrict__ A,
                                          const float* __restrict__ B,
                                          float* __restrict__ C,
                                          int M, int N, int K) {
    __shared__ float As[GBK][GBM];   // transposed A tile
    __shared__ float Bs[GBK][GBN];

    const int tid = threadIdx.x;
    const int tx = tid & 15;          // 0..15 -> column groups
    const int ty = tid >> 4;          // 0..15 -> row groups
    const int rowBase = blockIdx.y * GBM;
    const int colBase = blockIdx.x * GBN;

    float acc[8][8];
#pragma unroll
    for (int i = 0; i < 8; i++)
#pragma unroll
        for (int j = 0; j < 8; j++) acc[i][j] = 0.f;

    for (int kt = 0; kt < K; kt += GBK) {
        // Load A tile (128 rows x 16 cols): 512 float4 / 256 threads = 2 each
#pragma unroll
        for (int i = 0; i < 2; i++) {
            int lin = tid + i * 256;       // 0..511
            int r = lin >> 2;              // 0..127
            int c4 = (lin & 3) * 4;        // 0,4,8,12
            float4 a = *(const float4*)&A[(size_t)(rowBase + r) * K + kt + c4];
            As[c4 + 0][r] = a.x;
            As[c4 + 1][r] = a.y;
            As[c4 + 2][r] = a.z;
            As[c4 + 3][r] = a.w;
        }
        // Load B tile (16 rows x 128 cols): 512 float4 / 256 threads = 2 each
#pragma unroll
        for (int i = 0; i < 2; i++) {
            int lin = tid + i * 256;       // 0..511
            int r = lin >> 5;              // 0..15
            int c4 = (lin & 31) * 4;       // 0..124
            *(float4*)&Bs[r][c4] = *(const float4*)&B[(size_t)(kt + r) * N + colBase + c4];
        }
        __syncthreads();

#pragma unroll
        for (int k = 0; k < GBK; k++) {
            float ra[8], rb[8];
            *(float4*)&ra[0] = *(const float4*)&As[k][ty * 8];
            *(float4*)&ra[4] = *(const float4*)&As[k][ty * 8 + 4];
            *(float4*)&rb[0] = *(const float4*)&Bs[k][tx * 8];
            *(float4*)&rb[4] = *(const float4*)&Bs[k][tx * 8 + 4];
#pragma unroll
            for (int i = 0; i < 8; i++)
#pragma unroll
                for (int j = 0; j < 8; j++) acc[i][j] += ra[i] * rb[j];
        }
        __syncthreads();
    }

    // Write back
#pragma unroll
    for (int i = 0; i < 8; i++) {
        int r = rowBase + ty * 8 + i;
        float* crow = &C[(size_t)r * N + colBase + tx * 8];
        *(float4*)&crow[0] = *(const float4*)&acc[i][0];
        *(float4*)&crow[4] = *(const float4*)&acc[i][4];
    }
}

// QKV projection: grid.z selects weight/output
__global__ __launch_bounds__(256) void qkv_gemm_kernel(const float* __restrict__ x,
                                                       const float* __restrict__ Wq,
                                                       const float* __restrict__ Wk,
                                                       const float* __restrict__ Wv) {
    const float* Bw = (blockIdx.z == 0) ? Wq : (blockIdx.z == 1) ? Wk : Wv;
    float* C = (blockIdx.z == 0) ? g_q : (blockIdx.z == 1) ? g_k : g_v;
    gemm_body(x, Bw, C, PM, PD, PD);
}

__global__ __launch_bounds__(256) void out_gemm_kernel(const float* __restrict__ Wout,
                                                       float* __restrict__ out) {
    gemm_body(g_o, Wout, out, PM, PD, PD);
}

// ---------------------------------------------------------------------------
// Flash attention (causal), fp32.
// Block: 128 threads, each thread owns ONE query row (q + O acc in registers).
// K/V tiles of 64 keys in SMEM; online softmax over 16-key chunks.
// grid: (L/128, H, B)
// ---------------------------------------------------------------------------
#define AT_BM 128
#define AT_BN 64

__global__ __launch_bounds__(128) void attn_kernel() {
    const int qb = blockIdx.x * AT_BM;
    const int h  = blockIdx.y;
    const int b  = blockIdx.z;
    const int t  = threadIdx.x;
    const int i  = qb + t;                    // this thread's query row

    __shared__ float4 k_sm[AT_BN][PDh / 4];   // [key][16]
    __shared__ float4 v_sm[AT_BN][PDh / 4];

    // Load q row into registers, pre-scaled by 1/sqrt(Dh)
    const float sc = 0.125f;
    const float4* qptr = (const float4*)(g_q + ((size_t)(b * PL + i)) * PD + h * PDh);
    float4 q[16];
#pragma unroll
    for (int e = 0; e < 16; e++) {
        float4 v = qptr[e];
        v.x *= sc; v.y *= sc; v.z *= sc; v.w *= sc;
        q[e] = v;
    }

    float4 acc[16];
#pragma unroll
    for (int e = 0; e < 16; e++) acc[e] = make_float4(0.f, 0.f, 0.f, 0.f);
    float m = -1e30f, l = 0.f;

    const int imax = qb + AT_BM - 1;

    for (int jb = 0; jb <= imax; jb += AT_BN) {
        // Cooperative K/V tile load: 64 rows x 16 float4 each.
        {
            int r = t >> 1;
            int half8 = (t & 1) * 8;
            const float4* kg = (const float4*)(g_k + ((size_t)(b * PL + jb + r)) * PD + h * PDh);
            const float4* vg = (const float4*)(g_v + ((size_t)(b * PL + jb + r)) * PD + h * PDh);
#pragma unroll
            for (int w = 0; w < 8; w++) {
                k_sm[r][half8 + w] = kg[half8 + w];
                v_sm[r][half8 + w] = vg[half8 + w];
            }
        }
        __syncthreads();

#pragma unroll
        for (int c = 0; c < 4; c++) {
            const int jstart = jb + c * 16;
            if (jstart <= i) {
                float s[16];
#pragma unroll
                for (int jj = 0; jj < 16; jj++) {
                    const int j = c * 16 + jj;
                    float s0 = 0.f, s1 = 0.f, s2 = 0.f, s3 = 0.f;
#pragma unroll
                    for (int e = 0; e < 16; e++) {
                        float4 kv = k_sm[j][e];
                        s0 += q[e].x * kv.x;
                        s1 += q[e].y * kv.y;
                        s2 += q[e].z * kv.z;
                        s3 += q[e].w * kv.w;
                    }
                    float sum = (s0 + s1) + (s2 + s3);
                    s[jj] = (jstart + jj <= i) ? sum : -1e30f;
                }
                // chunk max
                float cm = s[0];
#pragma unroll
                for (int jj = 1; jj < 16; jj++) cm = fmaxf(cm, s[jj]);
                float nm = fmaxf(m, cm);
                float corr = __expf(m - nm);
                l *= corr;
#pragma unroll
                for (int e = 0; e < 16; e++) {
                    acc[e].x *= corr; acc[e].y *= corr;
                    acc[e].z *= corr; acc[e].w *= corr;
                }
#pragma unroll
                for (int jj = 0; jj < 16; jj++) {
                    const int j = c * 16 + jj;
                    float p = __expf(s[jj] - nm);
                    l += p;
#pragma unroll
                    for (int e = 0; e < 16; e++) {
                        float4 vv = v_sm[j][e];
                        acc[e].x += p * vv.x;
                        acc[e].y += p * vv.y;
                        acc[e].z += p * vv.z;
                        acc[e].w += p * vv.w;
                    }
                }
                m = nm;
            }
        }
        __syncthreads();
    }

    const float inv = 1.f / l;
    float4* optr = (float4*)(g_o + ((size_t)(b * PL + i)) * PD + h * PDh);
#pragma unroll
    for (int e = 0; e < 16; e++) {
        float4 r;
        r.x = acc[e].x * inv; r.y = acc[e].y * inv;
        r.z = acc[e].z * inv; r.w = acc[e].w * inv;
        optr[e] = r;
    }
}

// ---------------------------------------------------------------------------
// Launch
// ---------------------------------------------------------------------------
extern "C" void kernel_launch(void* const* d_in, const int* in_sizes, int n_in,
                              void* d_out, int out_size) {
    const float* x    = (const float*)d_in[0];
    const float* Wq   = (const float*)d_in[1];
    const float* Wk   = (const float*)d_in[2];
    const float* Wv   = (const float*)d_in[3];
    const float* Wout = (const float*)d_in[4];
    float* out = (float*)d_out;

    // QKV projections: 3 GEMMs of (4096x1024)x(1024x1024)
    dim3 gemmGrid(PD / GBN, PM / GBM, 3);
    qkv_gemm_kernel<<<gemmGrid, 256>>>(x, Wq, Wk, Wv);

    // Causal flash attention
    dim3 attnGrid(PL / AT_BM, PH, PB);
    attn_kernel<<<attnGrid, 128>>>();

    // Output projection
    dim3 outGrid(PD / GBN, PM / GBM, 1);
    out_gemm_kernel<<<outGrid, 256>>>(Wout, out);
}

// round 11
// speedup vs baseline: 4.2484x; 4.2257x over previous
#include <cuda_runtime.h>
#include <cuda_bf16.h>
#include <cstdint>

#define PB 2
#define PL 2048
#define PD 1024
#define PH 16
#define PDh 64
#define PM (PB * PL)

// Pre-split bf16 hi/lo operands (device globals; no runtime alloc)
__device__ __nv_bfloat16 g_x_hi[PM * PD],  g_x_lo[PM * PD];
__device__ __nv_bfloat16 g_wq_hi[PD * PD], g_wq_lo[PD * PD];
__device__ __nv_bfloat16 g_wk_hi[PD * PD], g_wk_lo[PD * PD];
__device__ __nv_bfloat16 g_wv_hi[PD * PD], g_wv_lo[PD * PD];
__device__ __nv_bfloat16 g_wo_hi[PD * PD], g_wo_lo[PD * PD];
__device__ __nv_bfloat16 g_q_hi[PM * PD],  g_q_lo[PM * PD];
__device__ __nv_bfloat16 g_k_hi[PM * PD],  g_k_lo[PM * PD];
__device__ __nv_bfloat16 g_v_hi[PM * PD],  g_v_lo[PM * PD];
__device__ __nv_bfloat16 g_o_hi[PM * PD],  g_o_lo[PM * PD];

__device__ __forceinline__ uint32_t smem_u32(const void* p) {
    return (uint32_t)__cvta_generic_to_shared(p);
}
__device__ __forceinline__ void ldsm_x4(uint32_t& r0, uint32_t& r1, uint32_t& r2, uint32_t& r3, uint32_t a) {
    asm volatile("ldmatrix.sync.aligned.m8n8.x4.shared.b16 {%0,%1,%2,%3}, [%4];"
                 : "=r"(r0), "=r"(r1), "=r"(r2), "=r"(r3) : "r"(a));
}
__device__ __forceinline__ void ldsm_x4t(uint32_t& r0, uint32_t& r1, uint32_t& r2, uint32_t& r3, uint32_t a) {
    asm volatile("ldmatrix.sync.aligned.m8n8.x4.trans.shared.b16 {%0,%1,%2,%3}, [%4];"
                 : "=r"(r0), "=r"(r1), "=r"(r2), "=r"(r3) : "r"(a));
}
__device__ __forceinline__ void ldsm_x2t(uint32_t& r0, uint32_t& r1, uint32_t a) {
    asm volatile("ldmatrix.sync.aligned.m8n8.x2.trans.shared.b16 {%0,%1}, [%2];"
                 : "=r"(r0), "=r"(r1) : "r"(a));
}
__device__ __forceinline__ void mma_bf16(float* d, uint32_t a0, uint32_t a1, uint32_t a2, uint32_t a3,
                                         uint32_t b0, uint32_t b1) {
    asm volatile("mma.sync.aligned.m16n8k16.row.col.f32.bf16.bf16.f32 "
                 "{%0,%1,%2,%3}, {%4,%5,%6,%7}, {%8,%9}, {%0,%1,%2,%3};"
                 : "+f"(d[0]), "+f"(d[1]), "+f"(d[2]), "+f"(d[3])
                 : "r"(a0), "r"(a1), "r"(a2), "r"(a3), "r"(b0), "r"(b1));
}
__device__ __forceinline__ void split_pair(float x, float y, uint32_t& hi, uint32_t& lo) {
    __nv_bfloat162 h2, l2;
    h2.x = __float2bfloat16(x);
    h2.y = __float2bfloat16(y);
    l2.x = __float2bfloat16(x - __bfloat162float(h2.x));
    l2.y = __float2bfloat16(y - __bfloat162float(h2.y));
    hi = *reinterpret_cast<uint32_t*>(&h2);
    lo = *reinterpret_cast<uint32_t*>(&l2);
}

// ---------------------------------------------------------------------------
// fp32 -> bf16 hi/lo split of the 5 inputs
// ---------------------------------------------------------------------------
__global__ __launch_bounds__(256) void split_all_kernel(
    const float* __restrict__ x,  const float* __restrict__ wq,
    const float* __restrict__ wk, const float* __restrict__ wv,
    const float* __restrict__ wo) {
    const int which = blockIdx.y;
    const float* src; __nv_bfloat16 *hi, *lo; int n2;
    if      (which == 0) { src = x;  hi = g_x_hi;  lo = g_x_lo;  n2 = PM * PD / 2; }
    else if (which == 1) { src = wq; hi = g_wq_hi; lo = g_wq_lo; n2 = PD * PD / 2; }
    else if (which == 2) { src = wk; hi = g_wk_hi; lo = g_wk_lo; n2 = PD * PD / 2; }
    else if (which == 3) { src = wv; hi = g_wv_hi; lo = g_wv_lo; n2 = PD * PD / 2; }
    else                 { src = wo; hi = g_wo_hi; lo = g_wo_lo; n2 = PD * PD / 2; }
    for (int i = blockIdx.x * 256 + threadIdx.x; i < n2; i += gridDim.x * 256) {
        float2 v = ((const float2*)src)[i];
        uint32_t h, l;
        split_pair(v.x, v.y, h, l);
        ((uint32_t*)hi)[i] = h;
        ((uint32_t*)lo)[i] = l;
    }
}

// ---------------------------------------------------------------------------
// bf16x3 MMA GEMM: C[4096x1024] = A[4096x1024] * B[1024x1024] (both row-major)
// 128x128 tile, K-tile 32, 8 warps of 64x32. MODE 0: hi/lo out. MODE 1: fp32.
// ---------------------------------------------------------------------------
#define SA 40
#define SB 136

template<int MODE>
__device__ __forceinline__ void gemm_1024(
    const __nv_bfloat16* __restrict__ Ah, const __nv_bfloat16* __restrict__ Al,
    const __nv_bfloat16* __restrict__ Bh, const __nv_bfloat16* __restrict__ Bl,
    __nv_bfloat16* __restrict__ Ch, __nv_bfloat16* __restrict__ Cl,
    float* __restrict__ Cf) {

    __shared__ __align__(16) __nv_bfloat16 sAh[128 * SA], sAl[128 * SA];
    __shared__ __align__(16) __nv_bfloat16 sBh[32 * SB],  sBl[32 * SB];

    const int tid = threadIdx.x;
    const int lane = tid & 31, warp = tid >> 5;
    const int wm = (warp >> 2) * 64;
    const int wn = (warp & 3) * 32;
    const int rowBase = blockIdx.y * 128;
    const int colBase = blockIdx.x * 128;

    float acc[4][4][4];
#pragma unroll
    for (int mi = 0; mi < 4; mi++)
#pragma unroll
        for (int ni = 0; ni < 4; ni++)
#pragma unroll
            for (int j = 0; j < 4; j++) acc[mi][ni][j] = 0.f;

    const uint32_t* gAh = (const uint32_t*)Ah + (size_t)rowBase * 512;
    const uint32_t* gAl = (const uint32_t*)Al + (size_t)rowBase * 512;
    const uint32_t* gBh = (const uint32_t*)Bh + (colBase >> 1);
    const uint32_t* gBl = (const uint32_t*)Bl + (colBase >> 1);
    uint32_t* wAh = (uint32_t*)sAh; uint32_t* wAl = (uint32_t*)sAl;
    uint32_t* wBh = (uint32_t*)sBh; uint32_t* wBl = (uint32_t*)sBl;

    const int aRow  = (lane & 7) + ((lane >> 3) & 1) * 8;
    const int aCol8 = ((lane >> 4) & 1) * 8;
    const int bRow  = (lane & 7) + ((lane >> 3) & 1) * 8;
    const uint32_t baseAh = smem_u32(sAh), baseAl = smem_u32(sAl);
    const uint32_t baseBh = smem_u32(sBh), baseBl = smem_u32(sBl);

    for (int kt = 0; kt < 1024; kt += 32) {
        const uint32_t* pAh = gAh + (kt >> 1);
        const uint32_t* pAl = gAl + (kt >> 1);
#pragma unroll
        for (int i = 0; i < 8; i++) {               // A: 128 x 16 u32
            int w = tid + i * 256; int m = w >> 4, c = w & 15;
            wAh[m * 20 + c] = pAh[(size_t)m * 512 + c];
            wAl[m * 20 + c] = pAl[(size_t)m * 512 + c];
        }
        const uint32_t* pBh = gBh + (size_t)kt * 512;
        const uint32_t* pBl = gBl + (size_t)kt * 512;
#pragma unroll
        for (int i = 0; i < 8; i++) {               // B: 32 x 64 u32
            int w = tid + i * 256; int k = w >> 6, c = w & 63;
            wBh[k * 68 + c] = pBh[(size_t)k * 512 + c];
            wBl[k * 68 + c] = pBl[(size_t)k * 512 + c];
        }
        __syncthreads();

#pragma unroll
        for (int ks = 0; ks < 2; ks++) {
            uint32_t bh[4][2], bl[4][2];
#pragma unroll
            for (int ni = 0; ni < 4; ni++) {
                uint32_t off = (uint32_t)(((ks * 16 + bRow) * SB + wn + ni * 8) * 2);
                ldsm_x2t(bh[ni][0], bh[ni][1], baseBh + off);
                ldsm_x2t(bl[ni][0], bl[ni][1], baseBl + off);
            }
#pragma unroll
            for (int mi = 0; mi < 4; mi++) {
                uint32_t off = (uint32_t)(((wm + mi * 16 + aRow) * SA + ks * 16 + aCol8) * 2);
                uint32_t a0, a1, a2, a3, l0, l1, l2, l3;
                ldsm_x4(a0, a1, a2, a3, baseAh + off);
                ldsm_x4(l0, l1, l2, l3, baseAl + off);
#pragma unroll
                for (int ni = 0; ni < 4; ni++) {
                    mma_bf16(acc[mi][ni], a0, a1, a2, a3, bh[ni][0], bh[ni][1]);
                    mma_bf16(acc[mi][ni], l0, l1, l2, l3, bh[ni][0], bh[ni][1]);
                    mma_bf16(acc[mi][ni], a0, a1, a2, a3, bl[ni][0], bl[ni][1]);
                }
            }
        }
        __syncthreads();
    }

    const int g = lane >> 2, t0 = lane & 3;
#pragma unroll
    for (int mi = 0; mi < 4; mi++) {
        int r0 = rowBase + wm + mi * 16 + g;
#pragma unroll
        for (int ni = 0; ni < 4; ni++) {
            int col = colBase + wn + ni * 8 + 2 * t0;
            float c0 = acc[mi][ni][0], c1 = acc[mi][ni][1];
            float c2 = acc[mi][ni][2], c3 = acc[mi][ni][3];
            if (MODE == 1) {
                ((float2*)Cf)[((size_t)r0 * 1024 + col) >> 1]       = make_float2(c0, c1);
                ((float2*)Cf)[((size_t)(r0 + 8) * 1024 + col) >> 1] = make_float2(c2, c3);
            } else {
                uint32_t h, l;
                split_pair(c0, c1, h, l);
                ((uint32_t*)Ch)[(size_t)r0 * 512 + (col >> 1)] = h;
                ((uint32_t*)Cl)[(size_t)r0 * 512 + (col >> 1)] = l;
                split_pair(c2, c3, h, l);
                ((uint32_t*)Ch)[(size_t)(r0 + 8) * 512 + (col >> 1)] = h;
                ((uint32_t*)Cl)[(size_t)(r0 + 8) * 512 + (col >> 1)] = l;
            }
        }
    }
}

__global__ __launch_bounds__(256, 2) void qkv_mma_kernel() {
    const int z = blockIdx.z;
    if (z == 0)      gemm_1024<0>(g_x_hi, g_x_lo, g_wq_hi, g_wq_lo, g_q_hi, g_q_lo, nullptr);
    else if (z == 1) gemm_1024<0>(g_x_hi, g_x_lo, g_wk_hi, g_wk_lo, g_k_hi, g_k_lo, nullptr);
    else             gemm_1024<0>(g_x_hi, g_x_lo, g_wv_hi, g_wv_lo, g_v_hi, g_v_lo, nullptr);
}
__global__ __launch_bounds__(256, 2) void out_mma_kernel(float* __restrict__ out) {
    gemm_1024<1>(g_o_hi, g_o_lo, g_wo_hi, g_wo_lo, nullptr, nullptr, out);
}

// ---------------------------------------------------------------------------
// Tensor-core causal flash attention. 64 q-rows/block, 4 warps x 16 rows.
// ---------------------------------------------------------------------------
#define AKS 72

__global__ __launch_bounds__(128, 2) void attn_mma_kernel() {
    __shared__ __align__(16) __nv_bfloat16 skh[64 * AKS], skl[64 * AKS];
    __shared__ __align__(16) __nv_bfloat16 svh[64 * AKS], svl[64 * AKS];

    const int tid = threadIdx.x;
    const int lane = tid & 31, warp = tid >> 5;
    const int g = lane >> 2, t0 = lane & 3;
    const int h = blockIdx.y, b = blockIdx.z;
    const int qb = (int)(gridDim.x - 1 - blockIdx.x) * 64;   // heavy blocks first
    const int rowG = b * PL + qb + warp * 16;

    // Preload Q A-fragments (hi/lo), pre-scaled by 1/sqrt(Dh)=0.125 (exact in bf16)
    uint32_t qah[4][4], qal[4][4];
    {
        const uint32_t* qh32 = (const uint32_t*)g_q_hi;
        const uint32_t* ql32 = (const uint32_t*)g_q_lo;
        const __nv_bfloat162 sc2 = __float2bfloat162_rn(0.125f);
        size_t r0 = (size_t)(rowG + g) * 512, r1 = (size_t)(rowG + g + 8) * 512;
#pragma unroll
        for (int ks = 0; ks < 4; ks++) {
            int c = h * 32 + ks * 8 + t0;
            uint32_t v[8] = { qh32[r0 + c], qh32[r1 + c], qh32[r0 + c + 4], qh32[r1 + c + 4],
                              ql32[r0 + c], ql32[r1 + c], ql32[r0 + c + 4], ql32[r1 + c + 4] };
#pragma unroll
            for (int j = 0; j < 8; j++) {
                __nv_bfloat162 t = __hmul2(*reinterpret_cast<__nv_bfloat162*>(&v[j]), sc2);
                v[j] = *reinterpret_cast<uint32_t*>(&t);
            }
#pragma unroll
            for (int j = 0; j < 4; j++) { qah[ks][j] = v[j]; qal[ks][j] = v[j + 4]; }
        }
    }

    float oacc[8][4];
#pragma unroll
    for (int dn = 0; dn < 8; dn++)
#pragma unroll
        for (int j = 0; j < 4; j++) oacc[dn][j] = 0.f;
    float m0 = -1e30f, m1 = -1e30f, l0 = 0.f, l1 = 0.f;

    const uint32_t bKh = smem_u32(skh), bKl = smem_u32(skl);
    const uint32_t bVh = smem_u32(svh), bVl = smem_u32(svl);
    const int nA = lane & 7;                 // within-8 row
    const int sel8 = ((lane >> 3) & 1) * 8;  // +8 col (k) selector
    const int sel16 = ((lane >> 4) & 1);     // pair selector
    const int qrow = qb + warp * 16 + g;

    const uint32_t* gkh = (const uint32_t*)g_k_hi + (size_t)(b * PL) * 512 + h * 32;
    const uint32_t* gkl = (const uint32_t*)g_k_lo + (size_t)(b * PL) * 512 + h * 32;
    const uint32_t* gvh = (const uint32_t*)g_v_hi + (size_t)(b * PL) * 512 + h * 32;
    const uint32_t* gvl = (const uint32_t*)g_v_lo + (size_t)(b * PL) * 512 + h * 32;

    for (int jb = 0; jb <= qb; jb += 64) {
        // Load K/V tile (64 keys x 64 dims, hi/lo): 2 threads per row, 4 uint4 each
        {
            int r = tid >> 1, q4 = (tid & 1) * 4;
            size_t gr = (size_t)(jb + r) * 512;
            uint32_t sr = r * 36 + q4 * 4;   // u32 index into smem row (AKS/2=36)
#pragma unroll
            for (int w = 0; w < 4; w++) {
                ((uint4*)((uint32_t*)skh + sr))[w] = ((const uint4*)(gkh + gr))[q4 + w];
                ((uint4*)((uint32_t*)skl + sr))[w] = ((const uint4*)(gkl + gr))[q4 + w];
                ((uint4*)((uint32_t*)svh + sr))[w] = ((const uint4*)(gvh + gr))[q4 + w];
                ((uint4*)((uint32_t*)svl + sr))[w] = ((const uint4*)(gvl + gr))[q4 + w];
            }
        }
        __syncthreads();

        // ---- S = Q*K^T (16x64 per warp), 3-pass bf16 ----
        float s[8][4];
#pragma unroll
        for (int ni = 0; ni < 8; ni++)
#pragma unroll
            for (int j = 0; j < 4; j++) s[ni][j] = 0.f;

#pragma unroll
        for (int ks = 0; ks < 4; ks++) {
#pragma unroll
            for (int np = 0; np < 4; np++) {
                uint32_t off = (uint32_t)((((np * 2 + sel16) * 8 + nA) * AKS + ks * 16 + sel8) * 2);
                uint32_t kh0, kh1, kh2, kh3, kl0, kl1, kl2, kl3;
                ldsm_x4(kh0, kh1, kh2, kh3, bKh + off);
                ldsm_x4(kl0, kl1, kl2, kl3, bKl + off);
                mma_bf16(s[np * 2],     qah[ks][0], qah[ks][1], qah[ks][2], qah[ks][3], kh0, kh1);
                mma_bf16(s[np * 2],     qal[ks][0], qal[ks][1], qal[ks][2], qal[ks][3], kh0, kh1);
                mma_bf16(s[np * 2],     qah[ks][0], qah[ks][1], qah[ks][2], qah[ks][3], kl0, kl1);
                mma_bf16(s[np * 2 + 1], qah[ks][0], qah[ks][1], qah[ks][2], qah[ks][3], kh2, kh3);
                mma_bf16(s[np * 2 + 1], qal[ks][0], qal[ks][1], qal[ks][2], qal[ks][3], kh2, kh3);
                mma_bf16(s[np * 2 + 1], qah[ks][0], qah[ks][1], qah[ks][2], qah[ks][3], kl2, kl3);
            }
        }

        // Causal mask (diagonal tile only)
        if (jb == qb) {
            int r1 = qrow + 8;
#pragma unroll
            for (int ni = 0; ni < 8; ni++) {
                int k0 = jb + ni * 8 + 2 * t0;
                if (k0     > qrow) s[ni][0] = -1e30f;
                if (k0 + 1 > qrow) s[ni][1] = -1e30f;
                if (k0     > r1)   s[ni][2] = -1e30f;
                if (k0 + 1 > r1)   s[ni][3] = -1e30f;
            }
        }

        // ---- online softmax ----
        float cm0 = -1e30f, cm1 = -1e30f;
#pragma unroll
        for (int ni = 0; ni < 8; ni++) {
            cm0 = fmaxf(cm0, fmaxf(s[ni][0], s[ni][1]));
            cm1 = fmaxf(cm1, fmaxf(s[ni][2], s[ni][3]));
        }
        cm0 = fmaxf(cm0, __shfl_xor_sync(0xffffffffu, cm0, 1));
        cm0 = fmaxf(cm0, __shfl_xor_sync(0xffffffffu, cm0, 2));
        cm1 = fmaxf(cm1, __shfl_xor_sync(0xffffffffu, cm1, 1));
        cm1 = fmaxf(cm1, __shfl_xor_sync(0xffffffffu, cm1, 2));
        float nm0 = fmaxf(m0, cm0), nm1 = fmaxf(m1, cm1);
        float corr0 = __expf(m0 - nm0), corr1 = __expf(m1 - nm1);
        m0 = nm0; m1 = nm1;
        l0 *= corr0; l1 *= corr1;
#pragma unroll
        for (int dn = 0; dn < 8; dn++) {
            oacc[dn][0] *= corr0; oacc[dn][1] *= corr0;
            oacc[dn][2] *= corr1; oacc[dn][3] *= corr1;
        }
#pragma unroll
        for (int ni = 0; ni < 8; ni++) {
            s[ni][0] = __expf(s[ni][0] - nm0); s[ni][1] = __expf(s[ni][1] - nm0);
            s[ni][2] = __expf(s[ni][2] - nm1); s[ni][3] = __expf(s[ni][3] - nm1);
            l0 += s[ni][0] + s[ni][1];
            l1 += s[ni][2] + s[ni][3];
        }

        // P -> bf16 hi/lo A-fragments (C-frag layout == A-frag layout)
        uint32_t pah[4][4], pal[4][4];
#pragma unroll
        for (int ks2 = 0; ks2 < 4; ks2++) {
            split_pair(s[2 * ks2][0],     s[2 * ks2][1],     pah[ks2][0], pal[ks2][0]);
            split_pair(s[2 * ks2][2],     s[2 * ks2][3],     pah[ks2][1], pal[ks2][1]);
            split_pair(s[2 * ks2 + 1][0], s[2 * ks2 + 1][1], pah[ks2][2], pal[ks2][2]);
            split_pair(s[2 * ks2 + 1][2], s[2 * ks2 + 1][3], pah[ks2][3], pal[ks2][3]);
        }

        // ---- O += P*V, 3-pass bf16 ----
#pragma unroll
        for (int ks2 = 0; ks2 < 4; ks2++) {
#pragma unroll
            for (int dp = 0; dp < 4; dp++) {
                uint32_t off = (uint32_t)(((ks2 * 16 + nA + sel8) * AKS + (dp * 2 + sel16) * 8) * 2);
                uint32_t vh0, vh1, vh2, vh3, vl0, vl1, vl2, vl3;
                ldsm_x4t(vh0, vh1, vh2, vh3, bVh + off);
                ldsm_x4t(vl0, vl1, vl2, vl3, bVl + off);
                mma_bf16(oacc[dp * 2],     pah[ks2][0], pah[ks2][1], pah[ks2][2], pah[ks2][3], vh0, vh1);
                mma_bf16(oacc[dp * 2],     pal[ks2][0], pal[ks2][1], pal[ks2][2], pal[ks2][3], vh0, vh1);
                mma_bf16(oacc[dp * 2],     pah[ks2][0], pah[ks2][1], pah[ks2][2], pah[ks2][3], vl0, vl1);
                mma_bf16(oacc[dp * 2 + 1], pah[ks2][0], pah[ks2][1], pah[ks2][2], pah[ks2][3], vh2, vh3);
                mma_bf16(oacc[dp * 2 + 1], pal[ks2][0], pal[ks2][1], pal[ks2][2], pal[ks2][3], vh2, vh3);
                mma_bf16(oacc[dp * 2 + 1], pah[ks2][0], pah[ks2][1], pah[ks2][2], pah[ks2][3], vl2, vl3);
            }
        }
        __syncthreads();
    }

    // Row-sum reduce across the quad, normalize, write O as hi/lo
    l0 += __shfl_xor_sync(0xffffffffu, l0, 1);
    l0 += __shfl_xor_sync(0xffffffffu, l0, 2);
    l1 += __shfl_xor_sync(0xffffffffu, l1, 1);
    l1 += __shfl_xor_sync(0xffffffffu, l1, 2);
    float inv0 = 1.f / l0, inv1 = 1.f / l1;

    uint32_t* oh32 = (uint32_t*)g_o_hi;
    uint32_t* ol32 = (uint32_t*)g_o_lo;
    size_t r0 = (size_t)(rowG + g) * 512, r1 = (size_t)(rowG + g + 8) * 512;
#pragma unroll
    for (int dn = 0; dn < 8; dn++) {
        int c = h * 32 + dn * 4 + t0;
        uint32_t hh, ll;
        split_pair(oacc[dn][0] * inv0, oacc[dn][1] * inv0, hh, ll);
        oh32[r0 + c] = hh; ol32[r0 + c] = ll;
        split_pair(oacc[dn][2] * inv1, oacc[dn][3] * inv1, hh, ll);
        oh32[r1 + c] = hh; ol32[r1 + c] = ll;
    }
}

// ---------------------------------------------------------------------------
extern "C" void kernel_launch(void* const* d_in, const int* in_sizes, int n_in,
                              void* d_out, int out_size) {
    const float* x    = (const float*)d_in[0];
    const float* Wq   = (const float*)d_in[1];
    const float* Wk   = (const float*)d_in[2];
    const float* Wv   = (const float*)d_in[3];
    const float* Wout = (const float*)d_in[4];
    float* out = (float*)d_out;

    dim3 splitGrid(128, 5);
    split_all_kernel<<<splitGrid, 256>>>(x, Wq, Wk, Wv, Wout);

    dim3 gemmGrid(8, 32, 3);
    qkv_mma_kernel<<<gemmGrid, 256>>>();

    dim3 attnGrid(32, PH, PB);
    attn_mma_kernel<<<attnGrid, 128>>>();

    dim3 outGrid(8, 32, 1);
    out_mma_kernel<<<outGrid, 256>>>(out);
}